// round 2
// baseline (speedup 1.0000x reference)
#include <cuda_runtime.h>

// Problem dims (fixed by the dataset)
#define BB     8
#define FF     8192
#define NLAT   64
#define DD     1024
#define HH     8
#define DHD    64
#define INNER  512
#define KVLEN  (FF + NLAT)          // 8256
#define NSPLIT 16
#define JT     32                    // kv tile in attention
#define NTILES (KVLEN / JT)          // 258
#define TPS    ((NTILES + NSPLIT - 1) / NSPLIT)  // 17
#define LN_EPS 1e-5f

// -------- scratch (device globals; no allocations allowed) --------
__device__ float  g_lat_ln[BB * NLAT * DD];                       // 2 MB
__device__ float2 g_stats[BB * FF];                               // 0.5 MB
__device__ float  g_kv[(size_t)BB * KVLEN * 1024];                // 270 MB: cols 0..511 = K, 512..1023 = V
__device__ float  g_qmat[BB * NLAT * INNER];                      // scaled Q, 1 MB
__device__ float  g_attnout[BB * NLAT * INNER];                   // 1 MB
__device__ float  g_pacc[(size_t)BB * HH * NSPLIT * NLAT * DHD];  // 16.8 MB
__device__ float  g_pm[BB * HH * NSPLIT * NLAT];
__device__ float  g_pl[BB * HH * NSPLIT * NLAT];
__device__ int    g_mask_is_byte;

// ---- mask dtype detector: int32 bool (words all <=1) vs byte bool ----
__global__ void detect_mask_kernel(const unsigned int* __restrict__ m) {
    unsigned int acc = 0;
    #pragma unroll
    for (int i = 0; i < 64; i++) acc |= m[i];
    g_mask_is_byte = (acc > 1u) ? 1 : 0;
}

// ---- LayerNorm of latents (writes g_lat_ln, gamma/beta applied) ----
__global__ __launch_bounds__(256) void ln_lat_kernel(const float* __restrict__ lat,
                                                     const float* __restrict__ gamma,
                                                     const float* __restrict__ beta) {
    int row = blockIdx.x;                 // 0..511 = b*64+q
    int t = threadIdx.x;
    const float* src = lat + (size_t)row * DD;
    float4 v = ((const float4*)src)[t];
    __shared__ float rs[256], rq[256];
    rs[t] = v.x + v.y + v.z + v.w;
    rq[t] = v.x*v.x + v.y*v.y + v.z*v.z + v.w*v.w;
    __syncthreads();
    for (int off = 128; off > 0; off >>= 1) {
        if (t < off) { rs[t] += rs[t + off]; rq[t] += rq[t + off]; }
        __syncthreads();
    }
    float mu   = rs[0] * (1.f / DD);
    float var  = rq[0] * (1.f / DD) - mu * mu;
    float rstd = rsqrtf(var + LN_EPS);
    float4 gv = ((const float4*)gamma)[t];
    float4 bv = ((const float4*)beta)[t];
    float4 o;
    o.x = (v.x - mu) * rstd * gv.x + bv.x;
    o.y = (v.y - mu) * rstd * gv.y + bv.y;
    o.z = (v.z - mu) * rstd * gv.z + bv.z;
    o.w = (v.w - mu) * rstd * gv.w + bv.w;
    ((float4*)(g_lat_ln + (size_t)row * DD))[t] = o;
}

// ---- per-row mean/rstd of x (LN applied lazily inside the GEMM) ----
__global__ __launch_bounds__(256) void x_stats_kernel(const float* __restrict__ x) {
    int row = blockIdx.x;                 // 0..65535 = b*FF+r
    int t = threadIdx.x;
    const float* src = x + (size_t)row * DD;
    float4 v = ((const float4*)src)[t];
    __shared__ float rs[256], rq[256];
    rs[t] = v.x + v.y + v.z + v.w;
    rq[t] = v.x*v.x + v.y*v.y + v.z*v.z + v.w*v.w;
    __syncthreads();
    for (int off = 128; off > 0; off >>= 1) {
        if (t < off) { rs[t] += rs[t + off]; rq[t] += rq[t + off]; }
        __syncthreads();
    }
    if (t == 0) {
        float mu  = rs[0] * (1.f / DD);
        float var = rq[0] * (1.f / DD) - mu * mu;
        g_stats[row] = make_float2(mu, rsqrtf(var + LN_EPS));
    }
}

// ---- fused LN + K/V projection GEMM ----
// C[M=BB*KVLEN, N=1024] = A_ln @ [Wk | Wv], A_ln rows: x rows (LN on the fly)
// or latent rows (g_lat_ln * kv_gate). BM=BN=128, BK=8, 256 thr, 8x8 microtile.
__global__ __launch_bounds__(256) void kv_gemm_kernel(const float* __restrict__ x,
                                                      const float* __restrict__ gm,
                                                      const float* __restrict__ bm,
                                                      const float* __restrict__ Wk,
                                                      const float* __restrict__ Wv,
                                                      const float* __restrict__ gate_p) {
    __shared__ float As[8][128];   // transposed: As[k][m]
    __shared__ float Bs[8][128];
    int t = threadIdx.x;
    int ntile = blockIdx.x;        // 0..7  (0..3 -> Wk, 4..7 -> Wv)
    int mtile = blockIdx.y;        // 0..515
    int tx = t & 15, ty = t >> 4;

    // A-load assignment: one global row per thread, fixed for whole block
    int arow = t >> 1;
    int ak   = (t & 1) * 4;
    size_t R = (size_t)mtile * 128 + arow;
    int b = (int)(R / KVLEN);
    int r = (int)(R % KVLEN);
    bool isx = (r < FF);
    const float* aptr;
    float mu = 0.f, rstd = 0.f, gate = 1.f;
    if (isx) {
        aptr = x + ((size_t)b * FF + r) * DD;
        float2 st = g_stats[b * FF + r];
        mu = st.x; rstd = st.y;
    } else {
        aptr = g_lat_ln + ((size_t)b * NLAT + (r - FF)) * DD;
        gate = gate_p[0];
    }

    // B-load assignment
    const float* Bsrc = (ntile < 4) ? Wk : Wv;
    int nb0 = (ntile & 3) * 128;
    int bk = t >> 5;
    int bn = (t & 31) * 4;

    float acc[8][8];
    #pragma unroll
    for (int i = 0; i < 8; i++)
        #pragma unroll
        for (int j = 0; j < 8; j++) acc[i][j] = 0.f;

    for (int kt = 0; kt < DD / 8; kt++) {
        int k0 = kt * 8;
        float4 av = *(const float4*)(aptr + k0 + ak);
        if (isx) {
            float4 gv = *(const float4*)(gm + k0 + ak);
            float4 bv = *(const float4*)(bm + k0 + ak);
            av.x = (av.x - mu) * rstd * gv.x + bv.x;
            av.y = (av.y - mu) * rstd * gv.y + bv.y;
            av.z = (av.z - mu) * rstd * gv.z + bv.z;
            av.w = (av.w - mu) * rstd * gv.w + bv.w;
        } else {
            av.x *= gate; av.y *= gate; av.z *= gate; av.w *= gate;
        }
        float4 bvv = *(const float4*)(Bsrc + (size_t)(k0 + bk) * INNER + nb0 + bn);
        __syncthreads();
        As[ak + 0][arow] = av.x;
        As[ak + 1][arow] = av.y;
        As[ak + 2][arow] = av.z;
        As[ak + 3][arow] = av.w;
        *(float4*)&Bs[bk][bn] = bvv;
        __syncthreads();
        #pragma unroll
        for (int kk = 0; kk < 8; kk++) {
            float a[8], bb[8];
            *(float4*)&a[0]  = *(const float4*)&As[kk][ty * 8];
            *(float4*)&a[4]  = *(const float4*)&As[kk][ty * 8 + 4];
            *(float4*)&bb[0] = *(const float4*)&Bs[kk][tx * 8];
            *(float4*)&bb[4] = *(const float4*)&Bs[kk][tx * 8 + 4];
            #pragma unroll
            for (int i = 0; i < 8; i++)
                #pragma unroll
                for (int j = 0; j < 8; j++)
                    acc[i][j] = fmaf(a[i], bb[j], acc[i][j]);
        }
    }

    // write C -> g_kv
    #pragma unroll
    for (int i = 0; i < 8; i++) {
        size_t Rr = (size_t)mtile * 128 + ty * 8 + i;
        int b2 = (int)(Rr / KVLEN);
        int r2 = (int)(Rr % KVLEN);
        float* dst = g_kv + ((size_t)b2 * KVLEN + r2) * 1024 + ntile * 128 + tx * 8;
        float4 c0 = make_float4(acc[i][0], acc[i][1], acc[i][2], acc[i][3]);
        float4 c1 = make_float4(acc[i][4], acc[i][5], acc[i][6], acc[i][7]);
        *(float4*)dst       = c0;
        *(float4*)(dst + 4) = c1;
    }
}

// ---- generic small sgemm (mode 0: Q proj, mode 1: out proj) ----
// BM=BN=64, BK=16, 256 threads, 4x4 microtile. Exact-fit dims only.
__global__ __launch_bounds__(256) void sgemm_kernel(const float* __restrict__ Bmat,
                                                    float* __restrict__ Cext,
                                                    int M, int N, int K,
                                                    int lda, int ldb, int ldc,
                                                    float alpha, int mode) {
    const float* A = (mode == 0) ? g_lat_ln : g_attnout;
    float* C = (mode == 0) ? g_qmat : Cext;
    __shared__ float As[16][65];  // transposed As[k][m]
    __shared__ float Bs[16][65];
    int t = threadIdx.x;
    int tx = t & 15, ty = t >> 4;
    int n0 = blockIdx.x * 64;
    int m0 = blockIdx.y * 64;
    float acc[4][4] = {};
    for (int k0 = 0; k0 < K; k0 += 16) {
        #pragma unroll
        for (int l = 0; l < 4; l++) {
            int idx = t + l * 256;
            int row = idx >> 4, kk = idx & 15;
            As[kk][row] = A[(size_t)(m0 + row) * lda + k0 + kk];
        }
        #pragma unroll
        for (int l = 0; l < 4; l++) {
            int idx = t + l * 256;
            int kk = idx >> 6, col = idx & 63;
            Bs[kk][col] = Bmat[(size_t)(k0 + kk) * ldb + n0 + col];
        }
        __syncthreads();
        #pragma unroll
        for (int kk = 0; kk < 16; kk++) {
            float a[4], bb[4];
            #pragma unroll
            for (int i = 0; i < 4; i++) a[i]  = As[kk][ty * 4 + i];
            #pragma unroll
            for (int j = 0; j < 4; j++) bb[j] = Bs[kk][tx * 4 + j];
            #pragma unroll
            for (int i = 0; i < 4; i++)
                #pragma unroll
                for (int j = 0; j < 4; j++)
                    acc[i][j] = fmaf(a[i], bb[j], acc[i][j]);
        }
        __syncthreads();
    }
    #pragma unroll
    for (int i = 0; i < 4; i++)
        #pragma unroll
        for (int j = 0; j < 4; j++)
            C[(size_t)(m0 + ty * 4 + i) * ldc + n0 + tx * 4 + j] = alpha * acc[i][j];
}

// ---- split-KV flash attention, pass A: per-split partials ----
__global__ __launch_bounds__(256) void attn_pass_kernel(const void* __restrict__ mask_raw) {
    int split = blockIdx.x, h = blockIdx.y, b = blockIdx.z;
    __shared__ float QsT[64][68];   // QsT[k][q]
    __shared__ float KsT[64][36];   // KsT[k][j]
    __shared__ float Vs[JT][68];    // Vs[j][d]
    __shared__ float ST[JT][68];    // ST[j][q] (scores, then probs)
    __shared__ float sm_m[64], sm_l[64], sm_alpha[64], sm_mnew[64];
    __shared__ float sm_valid[JT];
    int t = threadIdx.x;
    int tx = t & 15, ty = t >> 4;
    const unsigned char* mask8 = (const unsigned char*)mask_raw;
    const int*           mask32 = (const int*)mask_raw;
    int is_byte = g_mask_is_byte;

    #pragma unroll
    for (int l = 0; l < 16; l++) {
        int idx = t + l * 256;           // 0..4095
        int q = idx >> 6, k = idx & 63;
        QsT[k][q] = g_qmat[(size_t)(b * NLAT + q) * INNER + h * DHD + k];
    }
    if (t < 64) { sm_m[t] = -1e30f; sm_l[t] = 0.f; }
    float acc[4][4] = {};
    int t0 = split * TPS;
    int tcnt = NTILES - t0;
    if (tcnt > TPS) tcnt = TPS;
    if (tcnt < 0) tcnt = 0;
    __syncthreads();

    for (int it = 0; it < tcnt; it++) {
        int j0 = (t0 + it) * JT;
        #pragma unroll
        for (int l = 0; l < 8; l++) {
            int idx = t + l * 256;       // 0..2047
            int j = idx >> 6, dh = idx & 63;
            const float* base = g_kv + ((size_t)b * KVLEN + j0 + j) * 1024 + h * DHD;
            KsT[dh][j] = base[dh];
            Vs[j][dh]  = base[512 + dh];
        }
        if (t < JT) {
            int row = j0 + t;
            bool valid;
            if (row >= FF) valid = true;
            else {
                int mv = is_byte ? (int)mask8[b * FF + row] : mask32[b * FF + row];
                valid = (mv == 0);
            }
            sm_valid[t] = valid ? 1.f : 0.f;
        }
        __syncthreads();

        // S = Q K^T : thread -> q = ty*4..+3, j = tx*2..+1
        {
            float s00=0.f,s01=0.f,s10=0.f,s11=0.f,s20=0.f,s21=0.f,s30=0.f,s31=0.f;
            #pragma unroll
            for (int k = 0; k < 64; k++) {
                float4 a = *(const float4*)&QsT[k][ty * 4];
                float2 kb = *(const float2*)&KsT[k][tx * 2];
                s00 = fmaf(a.x, kb.x, s00); s01 = fmaf(a.x, kb.y, s01);
                s10 = fmaf(a.y, kb.x, s10); s11 = fmaf(a.y, kb.y, s11);
                s20 = fmaf(a.z, kb.x, s20); s21 = fmaf(a.z, kb.y, s21);
                s30 = fmaf(a.w, kb.x, s30); s31 = fmaf(a.w, kb.y, s31);
            }
            int jA = tx * 2, jB = tx * 2 + 1, q0 = ty * 4;
            float vA = sm_valid[jA], vB = sm_valid[jB];
            ST[jA][q0 + 0] = (vA != 0.f) ? s00 : -1e30f;
            ST[jB][q0 + 0] = (vB != 0.f) ? s01 : -1e30f;
            ST[jA][q0 + 1] = (vA != 0.f) ? s10 : -1e30f;
            ST[jB][q0 + 1] = (vB != 0.f) ? s11 : -1e30f;
            ST[jA][q0 + 2] = (vA != 0.f) ? s20 : -1e30f;
            ST[jB][q0 + 2] = (vB != 0.f) ? s21 : -1e30f;
            ST[jA][q0 + 3] = (vA != 0.f) ? s30 : -1e30f;
            ST[jB][q0 + 3] = (vB != 0.f) ? s31 : -1e30f;
        }
        __syncthreads();

        if (t < 64) {
            float mx = -1e30f;
            #pragma unroll
            for (int j = 0; j < JT; j++) mx = fmaxf(mx, ST[j][t]);
            float mold = sm_m[t];
            float mnew = fmaxf(mold, mx);
            sm_mnew[t]  = mnew;
            sm_alpha[t] = __expf(mold - mnew);
            sm_m[t] = mnew;
        }
        __syncthreads();

        // P = exp(S - mnew), masked -> 0 (exact)
        {
            int q0 = ty * 4;
            #pragma unroll
            for (int jj = 0; jj < 2; jj++) {
                int j = tx * 2 + jj;
                float vmask = sm_valid[j];
                #pragma unroll
                for (int i = 0; i < 4; i++) {
                    float sv = ST[j][q0 + i];
                    ST[j][q0 + i] = (vmask != 0.f) ? __expf(sv - sm_mnew[q0 + i]) : 0.f;
                }
            }
        }
        __syncthreads();

        if (t < 64) {
            float ls = 0.f;
            #pragma unroll
            for (int j = 0; j < JT; j++) ls += ST[j][t];
            sm_l[t] = sm_l[t] * sm_alpha[t] + ls;
        }
        // acc = acc*alpha + P @ V (runs alongside the l update; reads only)
        {
            int q0 = ty * 4;
            float al[4];
            #pragma unroll
            for (int i = 0; i < 4; i++) al[i] = sm_alpha[q0 + i];
            #pragma unroll
            for (int i = 0; i < 4; i++)
                #pragma unroll
                for (int j = 0; j < 4; j++) acc[i][j] *= al[i];
            #pragma unroll
            for (int k = 0; k < JT; k++) {
                float4 p  = *(const float4*)&ST[k][q0];
                float4 vv = *(const float4*)&Vs[k][tx * 4];
                acc[0][0] = fmaf(p.x, vv.x, acc[0][0]); acc[0][1] = fmaf(p.x, vv.y, acc[0][1]);
                acc[0][2] = fmaf(p.x, vv.z, acc[0][2]); acc[0][3] = fmaf(p.x, vv.w, acc[0][3]);
                acc[1][0] = fmaf(p.y, vv.x, acc[1][0]); acc[1][1] = fmaf(p.y, vv.y, acc[1][1]);
                acc[1][2] = fmaf(p.y, vv.z, acc[1][2]); acc[1][3] = fmaf(p.y, vv.w, acc[1][3]);
                acc[2][0] = fmaf(p.z, vv.x, acc[2][0]); acc[2][1] = fmaf(p.z, vv.y, acc[2][1]);
                acc[2][2] = fmaf(p.z, vv.z, acc[2][2]); acc[2][3] = fmaf(p.z, vv.w, acc[2][3]);
                acc[3][0] = fmaf(p.w, vv.x, acc[3][0]); acc[3][1] = fmaf(p.w, vv.y, acc[3][1]);
                acc[3][2] = fmaf(p.w, vv.z, acc[3][2]); acc[3][3] = fmaf(p.w, vv.w, acc[3][3]);
            }
        }
        __syncthreads();
    }

    size_t pbase = ((((size_t)b * HH + h) * NSPLIT + split) * NLAT) * DHD;
    #pragma unroll
    for (int i = 0; i < 4; i++)
        #pragma unroll
        for (int j = 0; j < 4; j++)
            g_pacc[pbase + (size_t)(ty * 4 + i) * DHD + tx * 4 + j] = acc[i][j];
    if (t < 64) {
        size_t sb = (((size_t)b * HH + h) * NSPLIT + split) * NLAT + t;
        g_pm[sb] = sm_m[t];
        g_pl[sb] = sm_l[t];
    }
}

// ---- pass B: combine split partials -> attn output (b, q, h*64+d) ----
__global__ __launch_bounds__(64) void attn_combine_kernel() {
    int q = blockIdx.x, h = blockIdx.y, b = blockIdx.z;
    int d = threadIdx.x;
    size_t sb = (((size_t)b * HH + h) * NSPLIT) * NLAT + q;
    float mg = -1e30f;
    #pragma unroll
    for (int s = 0; s < NSPLIT; s++) mg = fmaxf(mg, g_pm[sb + (size_t)s * NLAT]);
    float denom = 0.f, a = 0.f;
    #pragma unroll
    for (int s = 0; s < NSPLIT; s++) {
        float w = __expf(g_pm[sb + (size_t)s * NLAT] - mg);
        denom += g_pl[sb + (size_t)s * NLAT] * w;
        a += g_pacc[((((size_t)b * HH + h) * NSPLIT + s) * NLAT + q) * DHD + d] * w;
    }
    g_attnout[((size_t)b * NLAT + q) * INNER + h * DHD + d] = a / denom;
}

extern "C" void kernel_launch(void* const* d_in, const int* in_sizes, int n_in,
                              void* d_out, int out_size) {
    const float* x    = (const float*)d_in[0];
    const float* lat  = (const float*)d_in[1];
    const void*  mask = d_in[2];
    const float* gate = (const float*)d_in[3];
    const float* gm   = (const float*)d_in[4];
    const float* bm   = (const float*)d_in[5];
    const float* gl   = (const float*)d_in[6];
    const float* bl   = (const float*)d_in[7];
    const float* Wq   = (const float*)d_in[8];
    const float* Wk   = (const float*)d_in[9];
    const float* Wv   = (const float*)d_in[10];
    const float* Wout = (const float*)d_in[11];
    float* out = (float*)d_out;

    detect_mask_kernel<<<1, 1>>>((const unsigned int*)mask);
    ln_lat_kernel<<<BB * NLAT, 256>>>(lat, gl, bl);
    x_stats_kernel<<<BB * FF, 256>>>(x);
    kv_gemm_kernel<<<dim3(8, (BB * KVLEN) / 128), 256>>>(x, gm, bm, Wk, Wv, gate);
    // Q = lat_ln @ Wq, scaled by DIM_HEAD^-0.5 = 0.125
    sgemm_kernel<<<dim3(INNER / 64, (BB * NLAT) / 64), 256>>>(
        Wq, nullptr, BB * NLAT, INNER, DD, DD, INNER, INNER, 0.125f, 0);
    attn_pass_kernel<<<dim3(NSPLIT, HH, BB), 256>>>(mask);
    attn_combine_kernel<<<dim3(NLAT, HH, BB), 64>>>();
    // out = attn_out @ Wout
    sgemm_kernel<<<dim3(DD / 64, (BB * NLAT) / 64), 256>>>(
        Wout, out, BB * NLAT, DD, INNER, INNER, DD, DD, 1.0f, 1);
}

// round 4
// speedup vs baseline: 1.7969x; 1.7969x over previous
#include <cuda_runtime.h>
#include <cuda_bf16.h>
#include <cstdint>

// Problem dims (fixed by the dataset)
#define BB     8
#define FF     8192
#define NLAT   64
#define DD     1024
#define HH     8
#define DHD    64
#define INNER  512
#define KVLEN  (FF + NLAT)          // 8256
#define MROWS  (BB * KVLEN)         // 66048
#define NSPLIT 16
#define JT     32                    // kv tile in attention
#define NTILES (KVLEN / JT)          // 258
#define TPS    ((NTILES + NSPLIT - 1) / NSPLIT)  // 17
#define LN_EPS 1e-5f

// ---------------- family-safe PTX helpers (sm_80-era; no 'a'-features) ------
__device__ __forceinline__ uint32_t smem_u32(const void* p) {
    uint32_t a;
    asm("{ .reg .u64 t; cvta.to.shared.u64 t, %1; cvt.u32.u64 %0, t; }" : "=r"(a) : "l"(p));
    return a;
}
__device__ __forceinline__ void cp_async16(uint32_t dst, const void* src) {
    asm volatile("cp.async.cg.shared.global [%0], [%1], 16;" :: "r"(dst), "l"(src));
}
#define CP_COMMIT() asm volatile("cp.async.commit_group;" ::: "memory")
#define CP_WAIT(n)  asm volatile("cp.async.wait_group %0;" :: "n"(n) : "memory")

__device__ __forceinline__ void ldsm_x4(uint32_t* r, uint32_t addr) {
    asm volatile("ldmatrix.sync.aligned.m8n8.x4.shared.b16 {%0,%1,%2,%3}, [%4];"
        : "=r"(r[0]), "=r"(r[1]), "=r"(r[2]), "=r"(r[3]) : "r"(addr));
}
__device__ __forceinline__ void mma16816(float* c, const uint32_t* a,
                                         uint32_t b0, uint32_t b1) {
    asm volatile(
        "mma.sync.aligned.m16n8k16.row.col.f32.bf16.bf16.f32 "
        "{%0,%1,%2,%3}, {%4,%5,%6,%7}, {%8,%9}, {%0,%1,%2,%3};"
        : "+f"(c[0]), "+f"(c[1]), "+f"(c[2]), "+f"(c[3])
        : "r"(a[0]), "r"(a[1]), "r"(a[2]), "r"(a[3]), "r"(b0), "r"(b1));
}

// -------- scratch (device globals; no allocations allowed) --------
__device__ float          g_lat_ln[BB * NLAT * DD];                       // 2 MB
__device__ __nv_bfloat16  g_ahi[(size_t)MROWS * DD];                      // 135 MB
__device__ __nv_bfloat16  g_alo[(size_t)MROWS * DD];                      // 135 MB
__device__ __nv_bfloat16  g_bhi[1024 * 1024];                             // 2 MB  [n][k]
__device__ __nv_bfloat16  g_blo[1024 * 1024];                             // 2 MB
__device__ float          g_kv[(size_t)MROWS * 1024];                     // 270 MB: cols 0..511 K, 512..1023 V
__device__ float          g_qmat[BB * NLAT * INNER];                      // 1 MB
__device__ float          g_attnout[BB * NLAT * INNER];                   // 1 MB
__device__ float          g_pacc[(size_t)BB * HH * NSPLIT * NLAT * DHD];  // 16.8 MB
__device__ float          g_pm[BB * HH * NSPLIT * NLAT];
__device__ float          g_pl[BB * HH * NSPLIT * NLAT];
__device__ int            g_mask_is_byte;

// ---- mask dtype detector: int32 bool (words all <=1) vs byte bool ----
__global__ void detect_mask_kernel(const unsigned int* __restrict__ m) {
    unsigned int acc = 0;
    #pragma unroll
    for (int i = 0; i < 64; i++) acc |= m[i];
    g_mask_is_byte = (acc > 1u) ? 1 : 0;
}

// ---- LayerNorm of latents (writes g_lat_ln, gamma/beta applied) ----
__global__ __launch_bounds__(256) void ln_lat_kernel(const float* __restrict__ lat,
                                                     const float* __restrict__ gamma,
                                                     const float* __restrict__ beta) {
    int row = blockIdx.x;
    int t = threadIdx.x;
    float4 v = ((const float4*)(lat + (size_t)row * DD))[t];
    __shared__ float rs[256], rq[256];
    rs[t] = v.x + v.y + v.z + v.w;
    rq[t] = v.x*v.x + v.y*v.y + v.z*v.z + v.w*v.w;
    __syncthreads();
    for (int off = 128; off > 0; off >>= 1) {
        if (t < off) { rs[t] += rs[t + off]; rq[t] += rq[t + off]; }
        __syncthreads();
    }
    float mu   = rs[0] * (1.f / DD);
    float var  = rq[0] * (1.f / DD) - mu * mu;
    float rstd = rsqrtf(var + LN_EPS);
    float4 gv = ((const float4*)gamma)[t];
    float4 bv = ((const float4*)beta)[t];
    float4 o;
    o.x = (v.x - mu) * rstd * gv.x + bv.x;
    o.y = (v.y - mu) * rstd * gv.y + bv.y;
    o.z = (v.z - mu) * rstd * gv.z + bv.z;
    o.w = (v.w - mu) * rstd * gv.w + bv.w;
    ((float4*)(g_lat_ln + (size_t)row * DD))[t] = o;
}

// ---- fused LN + bf16 hi/lo split of the KV input matrix A ----
__global__ __launch_bounds__(256) void prep_a_kernel(const float* __restrict__ x,
                                                     const float* __restrict__ gm_,
                                                     const float* __restrict__ bm_,
                                                     const float* __restrict__ gate_p) {
    int row = blockIdx.x;                 // 0..MROWS-1
    int b = row / KVLEN;
    int r = row - b * KVLEN;
    int t = threadIdx.x;
    float4 y;
    if (r < FF) {
        float4 v = ((const float4*)(x + ((size_t)b * FF + r) * DD))[t];
        __shared__ float rs[256], rq[256];
        rs[t] = v.x + v.y + v.z + v.w;
        rq[t] = v.x*v.x + v.y*v.y + v.z*v.z + v.w*v.w;
        __syncthreads();
        for (int off = 128; off > 0; off >>= 1) {
            if (t < off) { rs[t] += rs[t + off]; rq[t] += rq[t + off]; }
            __syncthreads();
        }
        float mu   = rs[0] * (1.f / DD);
        float var  = rq[0] * (1.f / DD) - mu * mu;
        float rstd = rsqrtf(var + LN_EPS);
        float4 gv = ((const float4*)gm_)[t];
        float4 bv = ((const float4*)bm_)[t];
        y.x = (v.x - mu) * rstd * gv.x + bv.x;
        y.y = (v.y - mu) * rstd * gv.y + bv.y;
        y.z = (v.z - mu) * rstd * gv.z + bv.z;
        y.w = (v.w - mu) * rstd * gv.w + bv.w;
    } else {
        float4 v = ((const float4*)(g_lat_ln + ((size_t)b * NLAT + (r - FF)) * DD))[t];
        float gate = gate_p[0];
        y.x = v.x * gate; y.y = v.y * gate; y.z = v.z * gate; y.w = v.w * gate;
    }
    __nv_bfloat162 h01 = __floats2bfloat162_rn(y.x, y.y);
    __nv_bfloat162 h23 = __floats2bfloat162_rn(y.z, y.w);
    float lx = y.x - __bfloat162float(h01.x);
    float ly = y.y - __bfloat162float(h01.y);
    float lz = y.z - __bfloat162float(h23.x);
    float lw = y.w - __bfloat162float(h23.y);
    __nv_bfloat162 l01 = __floats2bfloat162_rn(lx, ly);
    __nv_bfloat162 l23 = __floats2bfloat162_rn(lz, lw);
    __nv_bfloat162* dh = (__nv_bfloat162*)(g_ahi + (size_t)row * DD) + 2 * t;
    __nv_bfloat162* dl = (__nv_bfloat162*)(g_alo + (size_t)row * DD) + 2 * t;
    dh[0] = h01; dh[1] = h23;
    dl[0] = l01; dl[1] = l23;
}

// ---- transpose [Wk|Wv] (k-major [1024][512] each) into B[n][k] bf16 hi/lo ----
__global__ __launch_bounds__(256) void prep_w_kernel(const float* __restrict__ Wk,
                                                     const float* __restrict__ Wv) {
    __shared__ float tile[32][33];
    int n0 = blockIdx.x * 32;           // 0..1023 (n of concat)
    int k0 = blockIdx.y * 32;
    int tx = threadIdx.x & 31, ty = threadIdx.x >> 5;  // 32 x 8
    const float* W = (n0 < 512) ? Wk : Wv;
    int nn0 = (n0 < 512) ? n0 : (n0 - 512);
    for (int i = ty; i < 32; i += 8)
        tile[i][tx] = W[(size_t)(k0 + i) * 512 + nn0 + tx];
    __syncthreads();
    for (int i = ty; i < 32; i += 8) {
        float v = tile[tx][i];          // = W[k0+tx][nn0+i]
        __nv_bfloat16 h = __float2bfloat16(v);
        __nv_bfloat16 l = __float2bfloat16(v - __bfloat162float(h));
        size_t idx = (size_t)(n0 + i) * 1024 + k0 + tx;
        g_bhi[idx] = h;
        g_blo[idx] = l;
    }
}

// ---- HMMA (mma.sync bf16) K/V projection: g_kv = A @ B^T, 3-term split ----
// BM=128, BN=128, BK=32. 256 thr = 8 warps (4m x 2n), warp tile 32x64.
// SMEM rows padded to 80B (40 halves) -> conflict-free ldmatrix.
#define AS_STRIDE_H 40                      // halves per SMEM row
#define MAT_BYTES   (128 * AS_STRIDE_H * 2) // 10240 per matrix tile
#define STG_BYTES   (4 * MAT_BYTES)         // 40960 per stage (Ah,Al,Bh,Bl)
#define GEMM_SMEM   (2 * STG_BYTES)         // 81920
#define NCHUNK      32

__global__ __launch_bounds__(256) void kv_mma_kernel() {
    extern __shared__ char smem[];
    const uint32_t sbase = smem_u32(smem);
    const int t = threadIdx.x;
    const int wid = t >> 5, lane = t & 31;
    const int ntile = blockIdx.x;            // 0..7
    const int mtile = blockIdx.y;            // 0..515
    const size_t arow0 = (size_t)mtile * 128;
    const int    brow0 = ntile * 128;

    // global load assignment: row r_ld, two consecutive 16B segs
    const int r_ld = t >> 1;
    const int seg0 = (t & 1) * 2;            // 0 or 2 (of 4 segs/row)
    const __nv_bfloat16* gAh = g_ahi + (arow0 + r_ld) * 1024 + seg0 * 8;
    const __nv_bfloat16* gAl = g_alo + (arow0 + r_ld) * 1024 + seg0 * 8;
    const __nv_bfloat16* gBh = g_bhi + (size_t)(brow0 + r_ld) * 1024 + seg0 * 8;
    const __nv_bfloat16* gBl = g_blo + (size_t)(brow0 + r_ld) * 1024 + seg0 * 8;
    const uint32_t sAdst = sbase + r_ld * 80 + seg0 * 16;   // + stage, + matrix off

    #define LOAD_CHUNK(chunk, buf) do {                                        \
        uint32_t sb_ = sAdst + (buf) * STG_BYTES;                              \
        int ko_ = (chunk) * 32;                                                \
        cp_async16(sb_ + 0 * MAT_BYTES,      gAh + ko_);                       \
        cp_async16(sb_ + 0 * MAT_BYTES + 16, gAh + ko_ + 8);                   \
        cp_async16(sb_ + 1 * MAT_BYTES,      gAl + ko_);                       \
        cp_async16(sb_ + 1 * MAT_BYTES + 16, gAl + ko_ + 8);                   \
        cp_async16(sb_ + 2 * MAT_BYTES,      gBh + ko_);                       \
        cp_async16(sb_ + 2 * MAT_BYTES + 16, gBh + ko_ + 8);                   \
        cp_async16(sb_ + 3 * MAT_BYTES,      gBl + ko_);                       \
        cp_async16(sb_ + 3 * MAT_BYTES + 16, gBl + ko_ + 8);                   \
    } while (0)

    // warp tile: wm in {0,32,64,96}, wn in {0,64}
    const int wm = (wid & 3) * 32;
    const int wn = (wid >> 2) * 64;

    // ldmatrix per-thread base offsets (halves)
    const int a_off_h = (wm + (lane & 15)) * AS_STRIDE_H + (lane >> 4) * 8;
    const int b_off_h = (wn + (lane & 7) + ((lane >> 3) & 1) * 8) * AS_STRIDE_H
                        + (lane >> 4) * 8;

    float acc[2][8][4];
    #pragma unroll
    for (int i = 0; i < 2; i++)
        #pragma unroll
        for (int j = 0; j < 8; j++)
            #pragma unroll
            for (int c = 0; c < 4; c++) acc[i][j][c] = 0.f;

    LOAD_CHUNK(0, 0);
    CP_COMMIT();

    for (int chunk = 0; chunk < NCHUNK; chunk++) {
        const int buf = chunk & 1;
        if (chunk + 1 < NCHUNK) {
            LOAD_CHUNK(chunk + 1, buf ^ 1);
            CP_COMMIT();
            CP_WAIT(1);
        } else {
            CP_WAIT(0);
        }
        __syncthreads();

        const uint32_t stg = sbase + buf * STG_BYTES;
        #pragma unroll
        for (int ks = 0; ks < 2; ks++) {
            uint32_t ah[2][4], al[2][4];
            #pragma unroll
            for (int mi = 0; mi < 2; mi++) {
                uint32_t ao = stg + (a_off_h + mi * 16 * AS_STRIDE_H + ks * 16) * 2;
                ldsm_x4(ah[mi], ao + 0 * MAT_BYTES);
                ldsm_x4(al[mi], ao + 1 * MAT_BYTES);
            }
            #pragma unroll
            for (int nip = 0; nip < 4; nip++) {
                uint32_t bh[4], bl[4];
                uint32_t bo = stg + (b_off_h + nip * 16 * AS_STRIDE_H + ks * 16) * 2;
                ldsm_x4(bh, bo + 2 * MAT_BYTES);
                ldsm_x4(bl, bo + 3 * MAT_BYTES);
                #pragma unroll
                for (int mi = 0; mi < 2; mi++) {
                    float* c0 = acc[mi][nip * 2];
                    float* c1 = acc[mi][nip * 2 + 1];
                    mma16816(c0, ah[mi], bh[0], bh[2]);
                    mma16816(c0, ah[mi], bl[0], bl[2]);
                    mma16816(c0, al[mi], bh[0], bh[2]);
                    mma16816(c1, ah[mi], bh[1], bh[3]);
                    mma16816(c1, ah[mi], bl[1], bl[3]);
                    mma16816(c1, al[mi], bh[1], bh[3]);
                }
            }
        }
        __syncthreads();
    }

    // epilogue: write fp32 C tile to g_kv
    const int col0 = ntile * 128 + wn + (lane & 3) * 2;
    #pragma unroll
    for (int mi = 0; mi < 2; mi++) {
        size_t row = arow0 + wm + mi * 16 + (lane >> 2);
        #pragma unroll
        for (int ni = 0; ni < 8; ni++) {
            float* d0 = g_kv + row * 1024 + col0 + ni * 8;
            float* d1 = g_kv + (row + 8) * 1024 + col0 + ni * 8;
            *(float2*)d0 = make_float2(acc[mi][ni][0], acc[mi][ni][1]);
            *(float2*)d1 = make_float2(acc[mi][ni][2], acc[mi][ni][3]);
        }
    }
}

// ---- generic small sgemm (mode 0: Q proj, mode 1: out proj) ----
__global__ __launch_bounds__(256) void sgemm_kernel(const float* __restrict__ Bmat,
                                                    float* __restrict__ Cext,
                                                    int M, int N, int K,
                                                    int lda, int ldb, int ldc,
                                                    float alpha, int mode) {
    const float* A = (mode == 0) ? g_lat_ln : g_attnout;
    float* C = (mode == 0) ? g_qmat : Cext;
    __shared__ float As[16][65];
    __shared__ float Bs[16][65];
    int t = threadIdx.x;
    int tx = t & 15, ty = t >> 4;
    int n0 = blockIdx.x * 64;
    int m0 = blockIdx.y * 64;
    float acc[4][4] = {};
    for (int k0 = 0; k0 < K; k0 += 16) {
        #pragma unroll
        for (int l = 0; l < 4; l++) {
            int idx = t + l * 256;
            int row = idx >> 4, kk = idx & 15;
            As[kk][row] = A[(size_t)(m0 + row) * lda + k0 + kk];
        }
        #pragma unroll
        for (int l = 0; l < 4; l++) {
            int idx = t + l * 256;
            int kk = idx >> 6, col = idx & 63;
            Bs[kk][col] = Bmat[(size_t)(k0 + kk) * ldb + n0 + col];
        }
        __syncthreads();
        #pragma unroll
        for (int kk = 0; kk < 16; kk++) {
            float a[4], bb[4];
            #pragma unroll
            for (int i = 0; i < 4; i++) a[i]  = As[kk][ty * 4 + i];
            #pragma unroll
            for (int j = 0; j < 4; j++) bb[j] = Bs[kk][tx * 4 + j];
            #pragma unroll
            for (int i = 0; i < 4; i++)
                #pragma unroll
                for (int j = 0; j < 4; j++)
                    acc[i][j] = fmaf(a[i], bb[j], acc[i][j]);
        }
        __syncthreads();
    }
    #pragma unroll
    for (int i = 0; i < 4; i++)
        #pragma unroll
        for (int j = 0; j < 4; j++)
            C[(size_t)(m0 + ty * 4 + i) * ldc + n0 + tx * 4 + j] = alpha * acc[i][j];
}

// ---- split-KV flash attention, pass A: per-split partials ----
__global__ __launch_bounds__(256) void attn_pass_kernel(const void* __restrict__ mask_raw) {
    int split = blockIdx.x, h = blockIdx.y, b = blockIdx.z;
    __shared__ float QsT[64][68];
    __shared__ float KsT[64][36];
    __shared__ float Vs[JT][68];
    __shared__ float ST[JT][68];
    __shared__ float sm_m[64], sm_l[64], sm_alpha[64], sm_mnew[64];
    __shared__ float sm_valid[JT];
    int t = threadIdx.x;
    int tx = t & 15, ty = t >> 4;
    const unsigned char* mask8 = (const unsigned char*)mask_raw;
    const int*           mask32 = (const int*)mask_raw;
    int is_byte = g_mask_is_byte;

    #pragma unroll
    for (int l = 0; l < 16; l++) {
        int idx = t + l * 256;
        int q = idx >> 6, k = idx & 63;
        QsT[k][q] = g_qmat[(size_t)(b * NLAT + q) * INNER + h * DHD + k];
    }
    if (t < 64) { sm_m[t] = -1e30f; sm_l[t] = 0.f; }
    float acc[4][4] = {};
    int t0 = split * TPS;
    int tcnt = NTILES - t0;
    if (tcnt > TPS) tcnt = TPS;
    if (tcnt < 0) tcnt = 0;
    __syncthreads();

    for (int it = 0; it < tcnt; it++) {
        int j0 = (t0 + it) * JT;
        #pragma unroll
        for (int l = 0; l < 8; l++) {
            int idx = t + l * 256;
            int j = idx >> 6, dh = idx & 63;
            const float* base = g_kv + ((size_t)b * KVLEN + j0 + j) * 1024 + h * DHD;
            KsT[dh][j] = base[dh];
            Vs[j][dh]  = base[512 + dh];
        }
        if (t < JT) {
            int row = j0 + t;
            bool valid;
            if (row >= FF) valid = true;
            else {
                int mv = is_byte ? (int)mask8[b * FF + row] : mask32[b * FF + row];
                valid = (mv == 0);
            }
            sm_valid[t] = valid ? 1.f : 0.f;
        }
        __syncthreads();

        {
            float s00=0.f,s01=0.f,s10=0.f,s11=0.f,s20=0.f,s21=0.f,s30=0.f,s31=0.f;
            #pragma unroll
            for (int k = 0; k < 64; k++) {
                float4 a = *(const float4*)&QsT[k][ty * 4];
                float2 kb = *(const float2*)&KsT[k][tx * 2];
                s00 = fmaf(a.x, kb.x, s00); s01 = fmaf(a.x, kb.y, s01);
                s10 = fmaf(a.y, kb.x, s10); s11 = fmaf(a.y, kb.y, s11);
                s20 = fmaf(a.z, kb.x, s20); s21 = fmaf(a.z, kb.y, s21);
                s30 = fmaf(a.w, kb.x, s30); s31 = fmaf(a.w, kb.y, s31);
            }
            int jA = tx * 2, jB = tx * 2 + 1, q0 = ty * 4;
            float vA = sm_valid[jA], vB = sm_valid[jB];
            ST[jA][q0 + 0] = (vA != 0.f) ? s00 : -1e30f;
            ST[jB][q0 + 0] = (vB != 0.f) ? s01 : -1e30f;
            ST[jA][q0 + 1] = (vA != 0.f) ? s10 : -1e30f;
            ST[jB][q0 + 1] = (vB != 0.f) ? s11 : -1e30f;
            ST[jA][q0 + 2] = (vA != 0.f) ? s20 : -1e30f;
            ST[jB][q0 + 2] = (vB != 0.f) ? s21 : -1e30f;
            ST[jA][q0 + 3] = (vA != 0.f) ? s30 : -1e30f;
            ST[jB][q0 + 3] = (vB != 0.f) ? s31 : -1e30f;
        }
        __syncthreads();

        if (t < 64) {
            float mx = -1e30f;
            #pragma unroll
            for (int j = 0; j < JT; j++) mx = fmaxf(mx, ST[j][t]);
            float mold = sm_m[t];
            float mnew = fmaxf(mold, mx);
            sm_mnew[t]  = mnew;
            sm_alpha[t] = __expf(mold - mnew);
            sm_m[t] = mnew;
        }
        __syncthreads();

        {
            int q0 = ty * 4;
            #pragma unroll
            for (int jj = 0; jj < 2; jj++) {
                int j = tx * 2 + jj;
                float vmask = sm_valid[j];
                #pragma unroll
                for (int i = 0; i < 4; i++) {
                    float sv = ST[j][q0 + i];
                    ST[j][q0 + i] = (vmask != 0.f) ? __expf(sv - sm_mnew[q0 + i]) : 0.f;
                }
            }
        }
        __syncthreads();

        if (t < 64) {
            float ls = 0.f;
            #pragma unroll
            for (int j = 0; j < JT; j++) ls += ST[j][t];
            sm_l[t] = sm_l[t] * sm_alpha[t] + ls;
        }
        {
            int q0 = ty * 4;
            float al[4];
            #pragma unroll
            for (int i = 0; i < 4; i++) al[i] = sm_alpha[q0 + i];
            #pragma unroll
            for (int i = 0; i < 4; i++)
                #pragma unroll
                for (int j = 0; j < 4; j++) acc[i][j] *= al[i];
            #pragma unroll
            for (int k = 0; k < JT; k++) {
                float4 p  = *(const float4*)&ST[k][q0];
                float4 vv = *(const float4*)&Vs[k][tx * 4];
                acc[0][0] = fmaf(p.x, vv.x, acc[0][0]); acc[0][1] = fmaf(p.x, vv.y, acc[0][1]);
                acc[0][2] = fmaf(p.x, vv.z, acc[0][2]); acc[0][3] = fmaf(p.x, vv.w, acc[0][3]);
                acc[1][0] = fmaf(p.y, vv.x, acc[1][0]); acc[1][1] = fmaf(p.y, vv.y, acc[1][1]);
                acc[1][2] = fmaf(p.y, vv.z, acc[1][2]); acc[1][3] = fmaf(p.y, vv.w, acc[1][3]);
                acc[2][0] = fmaf(p.z, vv.x, acc[2][0]); acc[2][1] = fmaf(p.z, vv.y, acc[2][1]);
                acc[2][2] = fmaf(p.z, vv.z, acc[2][2]); acc[2][3] = fmaf(p.z, vv.w, acc[2][3]);
                acc[3][0] = fmaf(p.w, vv.x, acc[3][0]); acc[3][1] = fmaf(p.w, vv.y, acc[3][1]);
                acc[3][2] = fmaf(p.w, vv.z, acc[3][2]); acc[3][3] = fmaf(p.w, vv.w, acc[3][3]);
            }
        }
        __syncthreads();
    }

    size_t pbase = ((((size_t)b * HH + h) * NSPLIT + split) * NLAT) * DHD;
    #pragma unroll
    for (int i = 0; i < 4; i++)
        #pragma unroll
        for (int j = 0; j < 4; j++)
            g_pacc[pbase + (size_t)(ty * 4 + i) * DHD + tx * 4 + j] = acc[i][j];
    if (t < 64) {
        size_t sb = (((size_t)b * HH + h) * NSPLIT + split) * NLAT + t;
        g_pm[sb] = sm_m[t];
        g_pl[sb] = sm_l[t];
    }
}

// ---- pass B: combine split partials -> attn output (b, q, h*64+d) ----
__global__ __launch_bounds__(64) void attn_combine_kernel() {
    int q = blockIdx.x, h = blockIdx.y, b = blockIdx.z;
    int d = threadIdx.x;
    size_t sb = (((size_t)b * HH + h) * NSPLIT) * NLAT + q;
    float mg = -1e30f;
    #pragma unroll
    for (int s = 0; s < NSPLIT; s++) mg = fmaxf(mg, g_pm[sb + (size_t)s * NLAT]);
    float denom = 0.f, a = 0.f;
    #pragma unroll
    for (int s = 0; s < NSPLIT; s++) {
        float w = __expf(g_pm[sb + (size_t)s * NLAT] - mg);
        denom += g_pl[sb + (size_t)s * NLAT] * w;
        a += g_pacc[((((size_t)b * HH + h) * NSPLIT + s) * NLAT + q) * DHD + d] * w;
    }
    g_attnout[((size_t)b * NLAT + q) * INNER + h * DHD + d] = a / denom;
}

extern "C" void kernel_launch(void* const* d_in, const int* in_sizes, int n_in,
                              void* d_out, int out_size) {
    const float* x    = (const float*)d_in[0];
    const float* lat  = (const float*)d_in[1];
    const void*  mask = d_in[2];
    const float* gate = (const float*)d_in[3];
    const float* gm   = (const float*)d_in[4];
    const float* bm   = (const float*)d_in[5];
    const float* gl   = (const float*)d_in[6];
    const float* bl   = (const float*)d_in[7];
    const float* Wq   = (const float*)d_in[8];
    const float* Wk   = (const float*)d_in[9];
    const float* Wv   = (const float*)d_in[10];
    const float* Wout = (const float*)d_in[11];
    float* out = (float*)d_out;

    cudaFuncSetAttribute(kv_mma_kernel,
                         cudaFuncAttributeMaxDynamicSharedMemorySize, GEMM_SMEM);

    detect_mask_kernel<<<1, 1>>>((const unsigned int*)mask);
    ln_lat_kernel<<<BB * NLAT, 256>>>(lat, gl, bl);
    prep_a_kernel<<<MROWS, 256>>>(x, gm, bm, gate);
    prep_w_kernel<<<dim3(32, 32), 256>>>(Wk, Wv);
    kv_mma_kernel<<<dim3(8, 516), 256, GEMM_SMEM>>>();
    // Q = lat_ln @ Wq, scaled by DIM_HEAD^-0.5 = 0.125
    sgemm_kernel<<<dim3(INNER / 64, (BB * NLAT) / 64), 256>>>(
        Wq, nullptr, BB * NLAT, INNER, DD, DD, INNER, INNER, 0.125f, 0);
    attn_pass_kernel<<<dim3(NSPLIT, HH, BB), 256>>>(mask);
    attn_combine_kernel<<<dim3(NLAT, HH, BB), 64>>>();
    sgemm_kernel<<<dim3(DD / 64, (BB * NLAT) / 64), 256>>>(
        Wout, out, BB * NLAT, DD, INNER, INNER, DD, DD, 1.0f, 1);
}